// round 1
// baseline (speedup 1.0000x reference)
#include <cuda_runtime.h>
#include <cuda_bf16.h>
#include <cstdint>

#define DEV_INLINE __device__ __forceinline__

constexpr int BATCH = 256;
constexpr int DIMC  = 384;
constexpr int NTOK  = 49;
constexpr int HEADS = 8;
constexpr int DVAL  = 128;
constexpr int NHKD  = 256;   // HEADS * 32
constexpr int DHCH  = 1024;  // HEADS * DVAL
constexpr int HID   = 1536;
constexpr int QKVC  = 1536;  // 256 + 256 + 1024

// ---------------- scratch (device globals; no runtime allocation) ----------
__device__ __nv_bfloat16 g_qkv   [BATCH * QKVC * NTOK];   // ch 0..255 q, 256..511 k, 512..1535 v
__device__ __nv_bfloat16 g_vlocal[BATCH * DHCH * NTOK];
__device__ __nv_bfloat16 g_opre  [BATCH * DHCH * NTOK];   // attn_out + v_local (pre-relu)
__device__ float         g_y     [BATCH * DIMC * NTOK];   // x + ls1 * proj(...)
__device__ __nv_bfloat16 g_h2    [BATCH * HID  * NTOK];   // relu(dw(relu(fc1)))

// ---------------- mma.sync bf16 m16n8k16 ----------------------------------
DEV_INLINE void mma_bf16(float c[4], uint32_t a0, uint32_t a1, uint32_t a2, uint32_t a3,
                         uint32_t b0, uint32_t b1) {
    asm volatile(
        "mma.sync.aligned.m16n8k16.row.col.f32.bf16.bf16.f32 "
        "{%0,%1,%2,%3},{%4,%5,%6,%7},{%8,%9},{%0,%1,%2,%3};\n"
        : "+f"(c[0]), "+f"(c[1]), "+f"(c[2]), "+f"(c[3])
        : "r"(a0), "r"(a1), "r"(a2), "r"(a3), "r"(b0), "r"(b1));
}

enum { M_QKV = 0, M_PROJ = 1, M_FC1 = 2, M_FC2 = 3 };

// Generic 1x1-conv GEMM over one image: out[o0..o0+63][0..48] = W @ X + bias,
// with mode-specific input transform + epilogue (dwconv / residual fusions).
template<int MODE, int K>
__global__ __launch_bounds__(256) void gemm1x1(
    const float* __restrict__ Wq, const float* __restrict__ Wk, const float* __restrict__ Wv,
    const float* __restrict__ Bq, const float* __restrict__ Bk, const float* __restrict__ Bv,
    const float* __restrict__ Xf,      // fp32 input (QKV: x)
    const float* __restrict__ dwW, const float* __restrict__ dwB,   // depthwise 3x3
    const float* __restrict__ resid,   // PROJ: x
    const float* __restrict__ lsv,     // ls1 / ls2
    float* __restrict__ outp)          // FC2: d_out
{
    __shared__ __nv_bfloat16 sA[64][40];   // [m][k]
    __shared__ __nv_bfloat16 sB[64][40];   // [n][k]
    __shared__ float sOut[64][50];

    const int b   = blockIdx.y;
    const int o0  = blockIdx.x * 64;
    const int tid = threadIdx.x;
    const int lane = tid & 31, warp = tid >> 5;
    const int wm = warp >> 2, wn = warp & 3;        // 2 x 4 warp grid
    const int gid = lane >> 2, tig = lane & 3;

    // weight / bias select (QKV tiles never straddle the 256/512 boundaries)
    const float* Wsel; const float* bsel; int wrow0;
    if (MODE == M_QKV) {
        if (o0 < 256)      { Wsel = Wq; bsel = Bq; wrow0 = o0; }
        else if (o0 < 512) { Wsel = Wk; bsel = Bk; wrow0 = o0 - 256; }
        else               { Wsel = Wv; bsel = Bv; wrow0 = o0 - 512; }
    } else { Wsel = Wq; bsel = Bq; wrow0 = o0; }

    float acc[2][2][4];
    #pragma unroll
    for (int mi = 0; mi < 2; mi++)
        #pragma unroll
        for (int ni = 0; ni < 2; ni++)
            #pragma unroll
            for (int r = 0; r < 4; r++) acc[mi][ni][r] = 0.f;

    for (int k0 = 0; k0 < K; k0 += 32) {
        // stage A (weights, fp32 -> bf16), coalesced along k
        #pragma unroll
        for (int i = 0; i < 8; i++) {
            int idx = tid + i * 256;
            int m = idx >> 5, kk = idx & 31;
            sA[m][kk] = __float2bfloat16(Wsel[(wrow0 + m) * K + k0 + kk]);
        }
        // stage B (activations), coalesced along n, transposed to [n][k]
        #pragma unroll
        for (int i = 0; i < 8; i++) {
            int idx = tid + i * 256;
            int n = idx & 63, c = idx >> 6;
            float v = 0.f;
            if (n < NTOK) {
                if (MODE == M_QKV)       v = Xf[(b * DIMC + k0 + c) * NTOK + n];
                else if (MODE == M_FC1)  v = g_y[(b * DIMC + k0 + c) * NTOK + n];
                else if (MODE == M_PROJ) {
                    v = __bfloat162float(g_opre[(b * DHCH + k0 + c) * NTOK + n]);
                    v = fmaxf(v, 0.f);   // relu before proj
                } else                   v = __bfloat162float(g_h2[(b * HID + k0 + c) * NTOK + n]);
            }
            sB[n][c] = __float2bfloat16(v);
        }
        __syncthreads();
        #pragma unroll
        for (int kk = 0; kk < 32; kk += 16) {
            uint32_t a[2][4], bb[2][2];
            #pragma unroll
            for (int mi = 0; mi < 2; mi++) {
                int r = wm * 32 + mi * 16 + gid;
                a[mi][0] = *(const uint32_t*)&sA[r    ][kk + 2 * tig];
                a[mi][1] = *(const uint32_t*)&sA[r + 8][kk + 2 * tig];
                a[mi][2] = *(const uint32_t*)&sA[r    ][kk + 2 * tig + 8];
                a[mi][3] = *(const uint32_t*)&sA[r + 8][kk + 2 * tig + 8];
            }
            #pragma unroll
            for (int ni = 0; ni < 2; ni++) {
                int cc = wn * 16 + ni * 8 + gid;
                bb[ni][0] = *(const uint32_t*)&sB[cc][kk + 2 * tig];
                bb[ni][1] = *(const uint32_t*)&sB[cc][kk + 2 * tig + 8];
            }
            #pragma unroll
            for (int mi = 0; mi < 2; mi++)
                #pragma unroll
                for (int ni = 0; ni < 2; ni++)
                    mma_bf16(acc[mi][ni], a[mi][0], a[mi][1], a[mi][2], a[mi][3],
                             bb[ni][0], bb[ni][1]);
        }
        __syncthreads();
    }

    // spill accumulators (+bias, relu for FC1) into the full [64][49] tile
    #pragma unroll
    for (int mi = 0; mi < 2; mi++) {
        #pragma unroll
        for (int ni = 0; ni < 2; ni++) {
            int r  = wm * 32 + mi * 16 + gid;
            int cb = wn * 16 + ni * 8 + tig * 2;
            float b0v = bsel[wrow0 + r];
            float b1v = bsel[wrow0 + r + 8];
            float v0 = acc[mi][ni][0] + b0v, v1 = acc[mi][ni][1] + b0v;
            float v2 = acc[mi][ni][2] + b1v, v3 = acc[mi][ni][3] + b1v;
            if (MODE == M_FC1) { v0 = fmaxf(v0, 0.f); v1 = fmaxf(v1, 0.f);
                                 v2 = fmaxf(v2, 0.f); v3 = fmaxf(v3, 0.f); }
            if (cb < NTOK)     { sOut[r][cb]     = v0; sOut[r + 8][cb]     = v2; }
            if (cb + 1 < NTOK) { sOut[r][cb + 1] = v1; sOut[r + 8][cb + 1] = v3; }
        }
    }
    __syncthreads();

    if (MODE == M_QKV) {
        for (int i = tid; i < 64 * NTOK; i += 256) {
            int m = i / NTOK, n = i % NTOK;
            g_qkv[(b * QKVC + o0 + m) * NTOK + n] = __float2bfloat16(sOut[m][n]);
        }
        if (o0 >= 512) {  // v channels: fused depthwise 3x3 -> v_local
            for (int i = tid; i < 64 * NTOK; i += 256) {
                int m = i / NTOK, n = i % NTOK;
                int ch = o0 - 512 + m;
                int pi = n / 7, pj = n % 7;
                float s = 0.f;
                #pragma unroll
                for (int di = 0; di < 3; di++)
                    #pragma unroll
                    for (int dj = 0; dj < 3; dj++) {
                        int ii = pi + di - 1, jj = pj + dj - 1;
                        if (ii >= 0 && ii < 7 && jj >= 0 && jj < 7)
                            s += dwW[ch * 9 + di * 3 + dj] * sOut[m][ii * 7 + jj];
                    }
                s += dwB[ch];
                g_vlocal[(b * DHCH + ch) * NTOK + n] = __float2bfloat16(s);
            }
        }
    } else if (MODE == M_PROJ) {
        for (int i = tid; i < 64 * NTOK; i += 256) {
            int m = i / NTOK, n = i % NTOK;
            int o = o0 + m;
            g_y[(b * DIMC + o) * NTOK + n] =
                resid[(b * DIMC + o) * NTOK + n] + lsv[o] * sOut[m][n];
        }
    } else if (MODE == M_FC1) {  // sOut holds relu(fc1); fused mid dwconv + relu
        for (int i = tid; i < 64 * NTOK; i += 256) {
            int m = i / NTOK, n = i % NTOK;
            int ch = o0 + m;
            int pi = n / 7, pj = n % 7;
            float s = 0.f;
            #pragma unroll
            for (int di = 0; di < 3; di++)
                #pragma unroll
                for (int dj = 0; dj < 3; dj++) {
                    int ii = pi + di - 1, jj = pj + dj - 1;
                    if (ii >= 0 && ii < 7 && jj >= 0 && jj < 7)
                        s += dwW[ch * 9 + di * 3 + dj] * sOut[m][ii * 7 + jj];
                }
            s = fmaxf(s + dwB[ch], 0.f);
            g_h2[(b * HID + ch) * NTOK + n] = __float2bfloat16(s);
        }
    } else {  // M_FC2: final output = y + ls2 * m
        for (int i = tid; i < 64 * NTOK; i += 256) {
            int m = i / NTOK, n = i % NTOK;
            int o = o0 + m;
            outp[(b * DIMC + o) * NTOK + n] =
                g_y[(b * DIMC + o) * NTOK + n] + lsv[o] * sOut[m][n];
        }
    }
}

// ---------------- attention megakernel: one CTA per image ------------------
__global__ __launch_bounds__(256) void attn_kernel(
    const float* __restrict__ attn_bias, const int* __restrict__ bias_idxs,
    const float* __restrict__ th1w, const float* __restrict__ th1b,
    const float* __restrict__ th2w, const float* __restrict__ th2b)
{
    extern __shared__ float sm[];
    float* S = sm;                  // [8][2401]  logits, later th2 output
    float* T = sm + 8 * 2401;       // [8][2401]  th1 output / softmax
    __nv_bfloat16* qs = (__nv_bfloat16*)(T + 8 * 2401);   // [32][49]
    __nv_bfloat16* ks = qs + 32 * NTOK;                   // [32][49]

    const int b = blockIdx.x;
    const int tid = threadIdx.x;
    const float scale = 0.17677669529663687f;   // 32^-0.5

    // S[h][n][m] = scale * sum_c q[h][c][n] k[h][c][m] + bias
    for (int h = 0; h < HEADS; h++) {
        __syncthreads();
        for (int i = tid; i < 32 * NTOK; i += 256) {
            int c = i / NTOK, n = i % NTOK;
            qs[i] = g_qkv[(b * QKVC +       h * 32 + c) * NTOK + n];
            ks[i] = g_qkv[(b * QKVC + 256 + h * 32 + c) * NTOK + n];
        }
        __syncthreads();
        for (int p = tid; p < 2401; p += 256) {
            int n = p / NTOK, m = p % NTOK;
            float s = 0.f;
            #pragma unroll
            for (int c = 0; c < 32; c++)
                s += __bfloat162float(qs[c * NTOK + n]) * __bfloat162float(ks[c * NTOK + m]);
            S[h * 2401 + p] = s * scale + attn_bias[h * NTOK + bias_idxs[p]];
        }
    }
    __syncthreads();
    // talking-heads 1
    for (int idx = tid; idx < HEADS * 2401; idx += 256) {
        int i = idx / 2401, p = idx % 2401;
        float t = th1b[i];
        #pragma unroll
        for (int j = 0; j < HEADS; j++) t += th1w[i * HEADS + j] * S[j * 2401 + p];
        T[idx] = t;
    }
    __syncthreads();
    // softmax over m
    for (int r = tid; r < HEADS * NTOK; r += 256) {
        float* row = T + (r / NTOK) * 2401 + (r % NTOK) * NTOK;
        float mx = row[0];
        for (int m2 = 1; m2 < NTOK; m2++) mx = fmaxf(mx, row[m2]);
        float sum = 0.f;
        for (int m2 = 0; m2 < NTOK; m2++) { float e = __expf(row[m2] - mx); row[m2] = e; sum += e; }
        float inv = 1.f / sum;
        for (int m2 = 0; m2 < NTOK; m2++) row[m2] *= inv;
    }
    __syncthreads();
    // talking-heads 2 -> S
    for (int idx = tid; idx < HEADS * 2401; idx += 256) {
        int i = idx / 2401, p = idx % 2401;
        float t = th2b[i];
        #pragma unroll
        for (int j = 0; j < HEADS; j++) t += th2w[i * HEADS + j] * T[j * 2401 + p];
        S[idx] = t;
    }
    __syncthreads();
    // o[h][d][n] = sum_m A[h][n][m] v[h][d][m] + v_local; warp-uniform smem reads
    const int d  = tid & 127;
    const int hh = tid >> 7;
    for (int h0 = 0; h0 < HEADS; h0 += 2) {
        int h  = h0 + hh;
        int ch = h * DVAL + d;
        const __nv_bfloat16* vp = g_qkv + (b * QKVC + 512 + ch) * NTOK;
        float vr[NTOK];
        #pragma unroll
        for (int m2 = 0; m2 < NTOK; m2++) vr[m2] = __bfloat162float(vp[m2]);
        const float* Ah = S + h * 2401;
        const __nv_bfloat16* vl = g_vlocal + (b * DHCH + ch) * NTOK;
        __nv_bfloat16* op = g_opre + (b * DHCH + ch) * NTOK;
        for (int n = 0; n < NTOK; n++) {
            float a2 = 0.f;
            #pragma unroll
            for (int m2 = 0; m2 < NTOK; m2++) a2 += Ah[n * NTOK + m2] * vr[m2];
            op[n] = __float2bfloat16(a2 + __bfloat162float(vl[n]));
        }
    }
}

// ---------------- launch ----------------------------------------------------
extern "C" void kernel_launch(void* const* d_in, const int* in_sizes, int n_in,
                              void* d_out, int out_size)
{
    const float* x      = (const float*)d_in[0];
    const float* q_w    = (const float*)d_in[1];
    const float* q_b    = (const float*)d_in[2];
    const float* k_w    = (const float*)d_in[3];
    const float* k_b    = (const float*)d_in[4];
    const float* v_w    = (const float*)d_in[5];
    const float* v_b    = (const float*)d_in[6];
    const float* lv_w   = (const float*)d_in[7];
    const float* lv_b   = (const float*)d_in[8];
    const float* th1_w  = (const float*)d_in[9];
    const float* th1_b  = (const float*)d_in[10];
    const float* th2_w  = (const float*)d_in[11];
    const float* th2_b  = (const float*)d_in[12];
    const float* attn_b = (const float*)d_in[13];
    const float* proj_w = (const float*)d_in[14];
    const float* proj_b = (const float*)d_in[15];
    const float* fc1_w  = (const float*)d_in[16];
    const float* fc1_b  = (const float*)d_in[17];
    const float* mid_w  = (const float*)d_in[18];
    const float* mid_b  = (const float*)d_in[19];
    const float* fc2_w  = (const float*)d_in[20];
    const float* fc2_b  = (const float*)d_in[21];
    const float* ls1    = (const float*)d_in[22];
    const float* ls2    = (const float*)d_in[23];
    const int*   bidx   = (const int*)d_in[24];
    float* outp = (float*)d_out;

    const int smem_attn = (2 * 8 * 2401) * 4 + (2 * 32 * NTOK) * 2;  // ~160 KB
    cudaFuncSetAttribute(attn_kernel, cudaFuncAttributeMaxDynamicSharedMemorySize, smem_attn);

    gemm1x1<M_QKV, 384><<<dim3(QKVC / 64, BATCH), 256>>>(
        q_w, k_w, v_w, q_b, k_b, v_b, x, lv_w, lv_b, nullptr, nullptr, nullptr);

    attn_kernel<<<BATCH, 256, smem_attn>>>(attn_b, bidx, th1_w, th1_b, th2_w, th2_b);

    gemm1x1<M_PROJ, 1024><<<dim3(DIMC / 64, BATCH), 256>>>(
        proj_w, nullptr, nullptr, proj_b, nullptr, nullptr,
        nullptr, nullptr, nullptr, x, ls1, nullptr);

    gemm1x1<M_FC1, 384><<<dim3(HID / 64, BATCH), 256>>>(
        fc1_w, nullptr, nullptr, fc1_b, nullptr, nullptr,
        nullptr, mid_w, mid_b, nullptr, nullptr, nullptr);

    gemm1x1<M_FC2, 1536><<<dim3(DIMC / 64, BATCH), 256>>>(
        fc2_w, nullptr, nullptr, fc2_b, nullptr, nullptr,
        nullptr, nullptr, nullptr, nullptr, ls2, outp);
}

// round 2
// speedup vs baseline: 1.3542x; 1.3542x over previous
#include <cuda_runtime.h>
#include <cuda_bf16.h>
#include <cstdint>

#define DEV_INLINE __device__ __forceinline__

constexpr int BATCH = 256;
constexpr int DIMC  = 384;
constexpr int NTOK  = 49;
constexpr int TPI   = 64;            // padded tokens per image
constexpr int T     = BATCH * TPI;   // 16384 global (padded) tokens
constexpr int HEADS = 8;
constexpr int DVAL  = 128;
constexpr int DHCH  = 1024;
constexpr int HID   = 1536;
constexpr int QKVC  = 1536;

// ---------------- scratch (device globals) ---------------------------------
__device__ __nv_bfloat16 g_wqkv [QKVC * DIMC];
__device__ __nv_bfloat16 g_wproj[DIMC * DHCH];
__device__ __nv_bfloat16 g_wfc1 [HID  * DIMC];
__device__ __nv_bfloat16 g_wfc2 [DIMC * HID];
__device__ float         g_bqkv [QKVC];
__device__ __nv_bfloat16 g_xt   [DIMC * T];    // bf16(x), token-padded
__device__ __nv_bfloat16 g_qkv  [QKVC * T];
__device__ __nv_bfloat16 g_vloc [DHCH * T];
__device__ __nv_bfloat16 g_attn [DHCH * T];    // relu(attn_out + v_local)
__device__ float         g_yf   [DIMC * T];    // y fp32 (residual source)
__device__ __nv_bfloat16 g_yb   [DIMC * T];    // y bf16 (FC1 operand)
__device__ __nv_bfloat16 g_h2   [HID  * T];    // relu(dw(relu(fc1)))

// ---------------- PTX helpers ----------------------------------------------
DEV_INLINE uint32_t smem_u32(const void* p) {
    return (uint32_t)__cvta_generic_to_shared(p);
}
DEV_INLINE void cp16(void* s, const void* g) {
    asm volatile("cp.async.ca.shared.global [%0], [%1], 16;\n"
                 :: "r"(smem_u32(s)), "l"(g));
}
DEV_INLINE void cp_commit() { asm volatile("cp.async.commit_group;\n"); }
DEV_INLINE void cp_wait1()  { asm volatile("cp.async.wait_group 1;\n"); }

DEV_INLINE void ldsm_x4(uint32_t r[4], uint32_t addr) {
    asm volatile("ldmatrix.sync.aligned.m8n8.x4.shared.b16 {%0,%1,%2,%3}, [%4];\n"
                 : "=r"(r[0]), "=r"(r[1]), "=r"(r[2]), "=r"(r[3]) : "r"(addr));
}
DEV_INLINE void ldsm_x4_t(uint32_t r[4], uint32_t addr) {
    asm volatile("ldmatrix.sync.aligned.m8n8.x4.trans.shared.b16 {%0,%1,%2,%3}, [%4];\n"
                 : "=r"(r[0]), "=r"(r[1]), "=r"(r[2]), "=r"(r[3]) : "r"(addr));
}
DEV_INLINE void mma_bf16(float c[4], const uint32_t a[4], uint32_t b0, uint32_t b1) {
    asm volatile(
        "mma.sync.aligned.m16n8k16.row.col.f32.bf16.bf16.f32 "
        "{%0,%1,%2,%3},{%4,%5,%6,%7},{%8,%9},{%0,%1,%2,%3};\n"
        : "+f"(c[0]), "+f"(c[1]), "+f"(c[2]), "+f"(c[3])
        : "r"(a[0]), "r"(a[1]), "r"(a[2]), "r"(a[3]), "r"(b0), "r"(b1));
}

// ---------------- prologue: weight/x conversion -----------------------------
constexpr int NW_QKV1 = 256 * 384;
constexpr int NW_QKV3 = 1024 * 384;
constexpr int NW_PROJ = 384 * 1024;
constexpr int NW_FCA  = 1536 * 384;
constexpr int NX      = BATCH * DIMC * NTOK;
constexpr long PTOTAL = (long)NW_QKV1 * 2 + NW_QKV3 + NW_PROJ + NW_FCA * 2 + 1536 + NX;

__global__ void prologue(const float* __restrict__ qw, const float* __restrict__ kw,
                         const float* __restrict__ vw, const float* __restrict__ qb,
                         const float* __restrict__ kb, const float* __restrict__ vb,
                         const float* __restrict__ pw, const float* __restrict__ f1w,
                         const float* __restrict__ f2w, const float* __restrict__ x)
{
    long i = (long)blockIdx.x * blockDim.x + threadIdx.x;
    if (i >= PTOTAL) return;
    if (i < NW_QKV1) { g_wqkv[i] = __float2bfloat16(qw[i]); return; }            i -= NW_QKV1;
    if (i < NW_QKV1) { g_wqkv[NW_QKV1 + i] = __float2bfloat16(kw[i]); return; }  i -= NW_QKV1;
    if (i < NW_QKV3) { g_wqkv[2 * NW_QKV1 + i] = __float2bfloat16(vw[i]); return; } i -= NW_QKV3;
    if (i < NW_PROJ) { g_wproj[i] = __float2bfloat16(pw[i]); return; }           i -= NW_PROJ;
    if (i < NW_FCA)  { g_wfc1[i] = __float2bfloat16(f1w[i]); return; }           i -= NW_FCA;
    if (i < NW_FCA)  { g_wfc2[i] = __float2bfloat16(f2w[i]); return; }           i -= NW_FCA;
    if (i < 256)  { g_bqkv[i] = qb[i]; return; }        i -= 256;
    if (i < 256)  { g_bqkv[256 + i] = kb[i]; return; }  i -= 256;
    if (i < 1024) { g_bqkv[512 + i] = vb[i]; return; }  i -= 1024;
    // x: [b][c][49] fp32 -> g_xt[c][b*64+n] bf16
    int b = (int)(i / (DIMC * NTOK));
    int r = (int)(i % (DIMC * NTOK));
    int c = r / NTOK, n = r % NTOK;
    g_xt[(size_t)c * T + b * TPI + n] = __float2bfloat16(x[i]);
}

// ---------------- big tiled GEMM: 128x128x32, cp.async + ldmatrix -----------
enum { M_QKV = 0, M_PROJ = 1, M_FC1 = 2, M_FC2 = 3 };

constexpr int SA_ELEM = 128 * 40;    // padded [128][40]
constexpr int SB_ELEM = 32 * 136;    // padded [32][136]
constexpr int STAGE_BYTES = (SA_ELEM + SB_ELEM) * 2;   // 18944
constexpr int GEMM_SMEM = 3 * STAGE_BYTES;             // 56832

template<int K>
DEV_INLINE void load_stage(char* smem_raw, int s, int k0, int m0, int t0, int tid,
                           const __nv_bfloat16* __restrict__ A,
                           const __nv_bfloat16* __restrict__ Bm)
{
    __nv_bfloat16* sA = (__nv_bfloat16*)(smem_raw + s * STAGE_BYTES);
    __nv_bfloat16* sB = (__nv_bfloat16*)(smem_raw + s * STAGE_BYTES + SA_ELEM * 2);
    #pragma unroll
    for (int i = 0; i < 2; i++) {
        int c = tid + i * 256;
        int row = c >> 2, part = c & 3;
        cp16(&sA[row * 40 + part * 8], &A[(size_t)(m0 + row) * K + k0 + part * 8]);
    }
    #pragma unroll
    for (int i = 0; i < 2; i++) {
        int c = tid + i * 256;
        int row = c >> 4, part = c & 15;
        cp16(&sB[row * 136 + part * 8], &Bm[(size_t)(k0 + row) * T + t0 + part * 8]);
    }
}

template<int MODE, int K>
__global__ __launch_bounds__(256) void gemm128(
    const float* __restrict__ bias,      // nullptr for QKV (uses g_bqkv)
    const float* __restrict__ dwW, const float* __restrict__ dwB,
    const float* __restrict__ xres, const float* __restrict__ ls,
    float* __restrict__ outp)
{
    static_assert(K % 32 == 0, "");
    extern __shared__ char smem_raw[];

    const int m0  = blockIdx.x * 128;
    const int t0  = blockIdx.y * 128;
    const int tid = threadIdx.x, lane = tid & 31, warp = tid >> 5;
    const int m0w = (warp >> 1) * 32, n0w = (warp & 1) * 64;
    const int gid = lane >> 2, tig = lane & 3;

    const __nv_bfloat16* A;
    const __nv_bfloat16* Bm;
    if constexpr (MODE == M_QKV)      { A = g_wqkv;  Bm = g_xt;   }
    else if constexpr (MODE == M_PROJ){ A = g_wproj; Bm = g_attn; }
    else if constexpr (MODE == M_FC1) { A = g_wfc1;  Bm = g_yb;   }
    else                              { A = g_wfc2;  Bm = g_h2;   }

    float acc[2][8][4];
    #pragma unroll
    for (int mi = 0; mi < 2; mi++)
        #pragma unroll
        for (int nj = 0; nj < 8; nj++)
            #pragma unroll
            for (int r = 0; r < 4; r++) acc[mi][nj][r] = 0.f;

    constexpr int KT = K / 32;
    load_stage<K>(smem_raw, 0, 0, m0, t0, tid, A, Bm);  cp_commit();
    load_stage<K>(smem_raw, 1, 32, m0, t0, tid, A, Bm); cp_commit();

    for (int it = 0; it < KT; ++it) {
        cp_wait1();
        __syncthreads();
        const __nv_bfloat16* sA = (const __nv_bfloat16*)(smem_raw + (it % 3) * STAGE_BYTES);
        const __nv_bfloat16* sB = (const __nv_bfloat16*)(smem_raw + (it % 3) * STAGE_BYTES + SA_ELEM * 2);
        #pragma unroll
        for (int kk = 0; kk < 32; kk += 16) {
            uint32_t a[2][4], bfr[4][4];
            #pragma unroll
            for (int mi = 0; mi < 2; mi++)
                ldsm_x4(a[mi], smem_u32(&sA[(m0w + mi * 16 + (lane & 15)) * 40 +
                                            kk + ((lane >> 4) << 3)]));
            #pragma unroll
            for (int ni = 0; ni < 4; ni++)
                ldsm_x4_t(bfr[ni], smem_u32(&sB[(kk + (lane & 7) + ((lane >> 3) & 1) * 8) * 136 +
                                                n0w + ni * 16 + ((lane >> 4) << 3)]));
            #pragma unroll
            for (int mi = 0; mi < 2; mi++)
                #pragma unroll
                for (int nj = 0; nj < 8; nj++)
                    mma_bf16(acc[mi][nj], a[mi],
                             bfr[nj >> 1][(nj & 1) ? 2 : 0],
                             bfr[nj >> 1][(nj & 1) ? 3 : 1]);
        }
        if (it + 2 < KT) load_stage<K>(smem_raw, (it + 2) % 3, (it + 2) * 32, m0, t0, tid, A, Bm);
        cp_commit();
    }

    // ---- stage accumulators (+bias, +relu for FC1) into sOut bf16[128][136]
    __syncthreads();
    __nv_bfloat16* sOut = (__nv_bfloat16*)smem_raw;
    float bs[2][2];
    #pragma unroll
    for (int mi = 0; mi < 2; mi++) {
        int r = m0 + m0w + mi * 16 + gid;
        if constexpr (MODE == M_QKV) { bs[mi][0] = g_bqkv[r]; bs[mi][1] = g_bqkv[r + 8]; }
        else                         { bs[mi][0] = bias[r];   bs[mi][1] = bias[r + 8];   }
    }
    #pragma unroll
    for (int mi = 0; mi < 2; mi++) {
        #pragma unroll
        for (int nj = 0; nj < 8; nj++) {
            int mrow = m0w + mi * 16 + gid;
            int ncol = n0w + nj * 8 + tig * 2;
            float v0 = acc[mi][nj][0] + bs[mi][0];
            float v1 = acc[mi][nj][1] + bs[mi][0];
            float v2 = acc[mi][nj][2] + bs[mi][1];
            float v3 = acc[mi][nj][3] + bs[mi][1];
            if constexpr (MODE == M_FC1) {
                v0 = fmaxf(v0, 0.f); v1 = fmaxf(v1, 0.f);
                v2 = fmaxf(v2, 0.f); v3 = fmaxf(v3, 0.f);
            }
            *(__nv_bfloat162*)&sOut[mrow * 136 + ncol] =
                __nv_bfloat162(__float2bfloat16(v0), __float2bfloat16(v1));
            *(__nv_bfloat162*)&sOut[(mrow + 8) * 136 + ncol] =
                __nv_bfloat162(__float2bfloat16(v2), __float2bfloat16(v3));
        }
    }
    __syncthreads();

    // ---- mode-specific epilogue over the [128][128] tile ----
    if constexpr (MODE == M_QKV) {
        for (int i = tid; i < 128 * 128; i += 256) {
            int m = i >> 7, nn = i & 127;
            g_qkv[(size_t)(m0 + m) * T + t0 + nn] = sOut[m * 136 + nn];
        }
        if (m0 >= 512) {  // v channels: fused depthwise 3x3 -> v_local
            for (int i = tid; i < 128 * 128; i += 256) {
                int m = i >> 7, nn = i & 127;
                int img = nn >> 6, n = nn & 63;
                if (n >= NTOK) continue;
                int ch = m0 + m - 512;
                int pi = n / 7, pj = n % 7;
                float s = 0.f;
                #pragma unroll
                for (int di = 0; di < 3; di++)
                    #pragma unroll
                    for (int dj = 0; dj < 3; dj++) {
                        int ii = pi + di - 1, jj = pj + dj - 1;
                        if (ii >= 0 && ii < 7 && jj >= 0 && jj < 7)
                            s += dwW[ch * 9 + di * 3 + dj] *
                                 __bfloat162float(sOut[m * 136 + img * TPI + ii * 7 + jj]);
                    }
                g_vloc[(size_t)ch * T + t0 + nn] = __float2bfloat16(s + dwB[ch]);
            }
        }
    } else if constexpr (MODE == M_PROJ) {
        for (int i = tid; i < 128 * 128; i += 256) {
            int m = i >> 7, nn = i & 127;
            int img = (t0 + nn) >> 6, n = nn & 63;
            if (n >= NTOK) continue;
            int ch = m0 + m;
            float o = __bfloat162float(sOut[m * 136 + nn]);
            float y = xres[((size_t)img * DIMC + ch) * NTOK + n] + ls[ch] * o;
            g_yf[(size_t)ch * T + t0 + nn] = y;
            g_yb[(size_t)ch * T + t0 + nn] = __float2bfloat16(y);
        }
    } else if constexpr (MODE == M_FC1) {
        for (int i = tid; i < 128 * 128; i += 256) {
            int m = i >> 7, nn = i & 127;
            int img = nn >> 6, n = nn & 63;
            if (n >= NTOK) continue;
            int ch = m0 + m;
            int pi = n / 7, pj = n % 7;
            float s = 0.f;
            #pragma unroll
            for (int di = 0; di < 3; di++)
                #pragma unroll
                for (int dj = 0; dj < 3; dj++) {
                    int ii = pi + di - 1, jj = pj + dj - 1;
                    if (ii >= 0 && ii < 7 && jj >= 0 && jj < 7)
                        s += dwW[ch * 9 + di * 3 + dj] *
                             __bfloat162float(sOut[m * 136 + img * TPI + ii * 7 + jj]);
                }
            s = fmaxf(s + dwB[ch], 0.f);
            g_h2[(size_t)ch * T + t0 + nn] = __float2bfloat16(s);
        }
    } else {  // M_FC2: final out = y + ls2 * m, original [b][c][49] fp32 layout
        for (int i = tid; i < 128 * 128; i += 256) {
            int m = i >> 7, nn = i & 127;
            int img = (t0 + nn) >> 6, n = nn & 63;
            if (n >= NTOK) continue;
            int ch = m0 + m;
            float mm = __bfloat162float(sOut[m * 136 + nn]);
            outp[((size_t)img * DIMC + ch) * NTOK + n] =
                g_yf[(size_t)ch * T + t0 + nn] + ls[ch] * mm;
        }
    }
}

// ---------------- attention megakernel: one CTA per image -------------------
__global__ __launch_bounds__(256) void attn_kernel(
    const float* __restrict__ attn_bias, const int* __restrict__ bias_idxs,
    const float* __restrict__ th1w, const float* __restrict__ th1b,
    const float* __restrict__ th2w, const float* __restrict__ th2b)
{
    extern __shared__ float sm[];
    float* S = sm;                  // [8][2401]
    float* Tm = sm + 8 * 2401;      // [8][2401]
    __nv_bfloat16* qs = (__nv_bfloat16*)(Tm + 8 * 2401);
    __nv_bfloat16* ks = qs + 32 * NTOK;

    const int b = blockIdx.x;
    const int tid = threadIdx.x;
    const float scale = 0.17677669529663687f;
    const size_t base = (size_t)b * TPI;

    for (int h = 0; h < HEADS; h++) {
        __syncthreads();
        for (int i = tid; i < 32 * NTOK; i += 256) {
            int c = i / NTOK, n = i % NTOK;
            qs[i] = g_qkv[(size_t)(h * 32 + c) * T + base + n];
            ks[i] = g_qkv[(size_t)(256 + h * 32 + c) * T + base + n];
        }
        __syncthreads();
        for (int p = tid; p < 2401; p += 256) {
            int n = p / NTOK, m = p % NTOK;
            float s = 0.f;
            #pragma unroll
            for (int c = 0; c < 32; c++)
                s += __bfloat162float(qs[c * NTOK + n]) * __bfloat162float(ks[c * NTOK + m]);
            S[h * 2401 + p] = s * scale + attn_bias[h * NTOK + bias_idxs[p]];
        }
    }
    __syncthreads();
    for (int idx = tid; idx < HEADS * 2401; idx += 256) {
        int i = idx / 2401, p = idx % 2401;
        float t = th1b[i];
        #pragma unroll
        for (int j = 0; j < HEADS; j++) t += th1w[i * HEADS + j] * S[j * 2401 + p];
        Tm[idx] = t;
    }
    __syncthreads();
    for (int r = tid; r < HEADS * NTOK; r += 256) {
        float* row = Tm + (r / NTOK) * 2401 + (r % NTOK) * NTOK;
        float mx = row[0];
        for (int m2 = 1; m2 < NTOK; m2++) mx = fmaxf(mx, row[m2]);
        float sum = 0.f;
        for (int m2 = 0; m2 < NTOK; m2++) { float e = __expf(row[m2] - mx); row[m2] = e; sum += e; }
        float inv = 1.f / sum;
        for (int m2 = 0; m2 < NTOK; m2++) row[m2] *= inv;
    }
    __syncthreads();
    for (int idx = tid; idx < HEADS * 2401; idx += 256) {
        int i = idx / 2401, p = idx % 2401;
        float t = th2b[i];
        #pragma unroll
        for (int j = 0; j < HEADS; j++) t += th2w[i * HEADS + j] * Tm[j * 2401 + p];
        S[idx] = t;
    }
    __syncthreads();
    const int d  = tid & 127;
    const int hh = tid >> 7;
    for (int h0 = 0; h0 < HEADS; h0 += 2) {
        int h  = h0 + hh;
        int ch = h * DVAL + d;
        const __nv_bfloat16* vp = g_qkv + (size_t)(512 + ch) * T + base;
        float vr[NTOK];
        #pragma unroll
        for (int m2 = 0; m2 < NTOK; m2++) vr[m2] = __bfloat162float(vp[m2]);
        const float* Ah = S + h * 2401;
        const __nv_bfloat16* vl = g_vloc + (size_t)ch * T + base;
        __nv_bfloat16* op = g_attn + (size_t)ch * T + base;
        for (int n = 0; n < NTOK; n++) {
            float a2 = 0.f;
            #pragma unroll
            for (int m2 = 0; m2 < NTOK; m2++) a2 += Ah[n * NTOK + m2] * vr[m2];
            op[n] = __float2bfloat16(fmaxf(a2 + __bfloat162float(vl[n]), 0.f));
        }
    }
}

// ---------------- launch ----------------------------------------------------
extern "C" void kernel_launch(void* const* d_in, const int* in_sizes, int n_in,
                              void* d_out, int out_size)
{
    const float* x      = (const float*)d_in[0];
    const float* q_w    = (const float*)d_in[1];
    const float* q_b    = (const float*)d_in[2];
    const float* k_w    = (const float*)d_in[3];
    const float* k_b    = (const float*)d_in[4];
    const float* v_w    = (const float*)d_in[5];
    const float* v_b    = (const float*)d_in[6];
    const float* lv_w   = (const float*)d_in[7];
    const float* lv_b   = (const float*)d_in[8];
    const float* th1_w  = (const float*)d_in[9];
    const float* th1_b  = (const float*)d_in[10];
    const float* th2_w  = (const float*)d_in[11];
    const float* th2_b  = (const float*)d_in[12];
    const float* attn_b = (const float*)d_in[13];
    const float* proj_w = (const float*)d_in[14];
    const float* proj_b = (const float*)d_in[15];
    const float* fc1_w  = (const float*)d_in[16];
    const float* fc1_b  = (const float*)d_in[17];
    const float* mid_w  = (const float*)d_in[18];
    const float* mid_b  = (const float*)d_in[19];
    const float* fc2_w  = (const float*)d_in[20];
    const float* fc2_b  = (const float*)d_in[21];
    const float* ls1    = (const float*)d_in[22];
    const float* ls2    = (const float*)d_in[23];
    const int*   bidx   = (const int*)d_in[24];
    float* outp = (float*)d_out;

    static bool attr_set = false;
    if (!attr_set) {
        cudaFuncSetAttribute(gemm128<M_QKV, 384>,  cudaFuncAttributeMaxDynamicSharedMemorySize, GEMM_SMEM);
        cudaFuncSetAttribute(gemm128<M_PROJ, 1024>, cudaFuncAttributeMaxDynamicSharedMemorySize, GEMM_SMEM);
        cudaFuncSetAttribute(gemm128<M_FC1, 384>,  cudaFuncAttributeMaxDynamicSharedMemorySize, GEMM_SMEM);
        cudaFuncSetAttribute(gemm128<M_FC2, 1536>, cudaFuncAttributeMaxDynamicSharedMemorySize, GEMM_SMEM);
        const int smem_attn = (2 * 8 * 2401) * 4 + (2 * 32 * NTOK) * 2;
        cudaFuncSetAttribute(attn_kernel, cudaFuncAttributeMaxDynamicSharedMemorySize, smem_attn);
        attr_set = true;
    }
    const int smem_attn = (2 * 8 * 2401) * 4 + (2 * 32 * NTOK) * 2;

    prologue<<<(int)((PTOTAL + 255) / 256), 256>>>(q_w, k_w, v_w, q_b, k_b, v_b,
                                                   proj_w, fc1_w, fc2_w, x);

    gemm128<M_QKV, 384><<<dim3(QKVC / 128, T / 128), 256, GEMM_SMEM>>>(
        nullptr, lv_w, lv_b, nullptr, nullptr, nullptr);

    attn_kernel<<<BATCH, 256, smem_attn>>>(attn_b, bidx, th1_w, th1_b, th2_w, th2_b);

    gemm128<M_PROJ, 1024><<<dim3(DIMC / 128, T / 128), 256, GEMM_SMEM>>>(
        proj_b, nullptr, nullptr, x, ls1, nullptr);

    gemm128<M_FC1, 384><<<dim3(HID / 128, T / 128), 256, GEMM_SMEM>>>(
        fc1_b, mid_w, mid_b, nullptr, nullptr, nullptr);

    gemm128<M_FC2, 1536><<<dim3(DIMC / 128, T / 128), 256, GEMM_SMEM>>>(
        fc2_b, nullptr, nullptr, nullptr, ls2, outp);
}